// round 14
// baseline (speedup 1.0000x reference)
#include <cuda_runtime.h>
#include <cuda_bf16.h>
#include <cstdint>

#define N_NODES 50000
#define N_EDGES 800000
#define SCAN_B  49   // ceil(50000/1024)

// ---------------- scratch (static __device__ globals; no allocation) ----------------
__device__ int   g_deg [N_NODES];
__device__ int   g_off [N_NODES + 1];
__device__ int   g_pos [N_NODES];
__device__ int   g_srcs[N_EDGES];
__device__ float g_inv [N_NODES];
__device__ int   g_bsum[64];

__device__ float g_h1 [(size_t)N_NODES * 128];   // fp32 (gathered by layer-2 agg)
__device__ float g_p  [(size_t)N_NODES * 32];
__device__ float g_q  [(size_t)N_NODES * 32];

// bf16 hi/lo planes (pre-split operands for mma GEMMs)
__device__ __align__(16) __nv_bfloat16 g_xh [(size_t)N_NODES * 128];
__device__ __align__(16) __nv_bfloat16 g_xl [(size_t)N_NODES * 128];
__device__ __align__(16) __nv_bfloat16 g_mh [(size_t)N_NODES * 128];
__device__ __align__(16) __nv_bfloat16 g_ml [(size_t)N_NODES * 128];
__device__ __align__(16) __nv_bfloat16 g_h1h[(size_t)N_NODES * 128];
__device__ __align__(16) __nv_bfloat16 g_h1l[(size_t)N_NODES * 128];
__device__ __align__(16) __nv_bfloat16 g_h2h[(size_t)N_NODES * 128];
__device__ __align__(16) __nv_bfloat16 g_h2l[(size_t)N_NODES * 128];
// packed W planes: [0,128)=Wl1 [128,256)=Wr1 [256,384)=Wl2 [384,512)=Wr2 [512,544)=Wl3 [544,576)=Wr3
#define WROWS 576
__device__ __align__(16) __nv_bfloat16 g_wh[WROWS * 128];
__device__ __align__(16) __nv_bfloat16 g_wl[WROWS * 128];

// ---------------- helpers ----------------
#define MMA_BF16(c, a, b) \
    asm volatile("mma.sync.aligned.m16n8k16.row.col.f32.bf16.bf16.f32 " \
        "{%0,%1,%2,%3}, {%4,%5,%6,%7}, {%8,%9}, {%0,%1,%2,%3};" \
        : "+f"((c)[0]), "+f"((c)[1]), "+f"((c)[2]), "+f"((c)[3]) \
        : "r"((a)[0]), "r"((a)[1]), "r"((a)[2]), "r"((a)[3]), \
          "r"((b)[0]), "r"((b)[1]))

__device__ __forceinline__ uint32_t pack_bf2(float a, float b) {
    __nv_bfloat162 h = __floats2bfloat162_rn(a, b);
    return *reinterpret_cast<uint32_t*>(&h);
}
__device__ __forceinline__ void split_pack4(float4 v, uint2& hi, uint2& lo) {
    float hx = __bfloat162float(__float2bfloat16(v.x));
    float hy = __bfloat162float(__float2bfloat16(v.y));
    float hz = __bfloat162float(__float2bfloat16(v.z));
    float hw = __bfloat162float(__float2bfloat16(v.w));
    hi = make_uint2(pack_bf2(hx, hy), pack_bf2(hz, hw));
    lo = make_uint2(pack_bf2(v.x - hx, v.y - hy), pack_bf2(v.z - hz, v.w - hw));
}
__device__ __forceinline__ void split2(float f0, float f1, uint32_t& hi, uint32_t& lo) {
    float h0 = __bfloat162float(__float2bfloat16(f0));
    float h1 = __bfloat162float(__float2bfloat16(f1));
    hi = pack_bf2(h0, h1);
    lo = pack_bf2(f0 - h0, f1 - h1);
}

// smem layout (bf16 elements), K=128 chunks, row stride 136 (272B, conflict pattern
// identical to the proven stride-72 layout: bank = 4*row + quad)
#define A_STRIDE 136
#define SM_AH 0
#define SM_AL 17408      // 128*136
#define SM_WH 34816
#define SM_WL 43520      // + 64*136
#define SMEM_MMA ((43520 + 8704) * 2)   // 104448 bytes; 2 CTAs = 208.9 KB < 228 KB

// ---------------- fused split(x,W) + degree count ----------------
#define X4 1600000          // 50000*128/4
#define W4 18432            // 576*128/4
__global__ void k_split_count(const float* __restrict__ x,
                              const float* __restrict__ Wl1, const float* __restrict__ Wr1,
                              const float* __restrict__ Wl2, const float* __restrict__ Wr2,
                              const float* __restrict__ Wl3, const float* __restrict__ Wr3,
                              const int* __restrict__ dst) {
    int i = blockIdx.x * blockDim.x + threadIdx.x;
    if (i < N_EDGES) atomicAdd(&g_deg[dst[i]], 1);
    if (i < X4) {
        float4 v = *(const float4*)(x + (size_t)i * 4);
        uint2 hi, lo; split_pack4(v, hi, lo);
        *(uint2*)(g_xh + (size_t)i * 4) = hi;
        *(uint2*)(g_xl + (size_t)i * 4) = lo;
    } else if (i < X4 + W4) {
        int wi = i - X4;
        int row = wi >> 5, c4 = wi & 31;
        const float* src;
        if      (row < 128) src = Wl1 + (size_t)row * 128;
        else if (row < 256) src = Wr1 + (size_t)(row - 128) * 128;
        else if (row < 384) src = Wl2 + (size_t)(row - 256) * 128;
        else if (row < 512) src = Wr2 + (size_t)(row - 384) * 128;
        else if (row < 544) src = Wl3 + (size_t)(row - 512) * 128;
        else                src = Wr3 + (size_t)(row - 544) * 128;
        float4 v = *(const float4*)(src + c4 * 4);
        uint2 hi, lo; split_pack4(v, hi, lo);
        *(uint2*)(g_wh + row * 128 + c4 * 4) = hi;
        *(uint2*)(g_wl + row * 128 + c4 * 4) = lo;
    }
}

// ---------------- CSR scan ----------------
__global__ void k_scan1() {
    __shared__ int wsum[32];
    int t = threadIdx.x, b = blockIdx.x;
    int i = b * 1024 + t;
    int v = (i < N_NODES) ? g_deg[i] : 0;
    int lane = t & 31, w = t >> 5;
    int x = v;
    #pragma unroll
    for (int o = 1; o < 32; o <<= 1) {
        int y = __shfl_up_sync(0xffffffffu, x, o);
        if (lane >= o) x += y;
    }
    if (lane == 31) wsum[w] = x;
    __syncthreads();
    if (w == 0) {
        int s = wsum[lane];
        #pragma unroll
        for (int o = 1; o < 32; o <<= 1) {
            int y = __shfl_up_sync(0xffffffffu, s, o);
            if (lane >= o) s += y;
        }
        wsum[lane] = s;
    }
    __syncthreads();
    int incl = x + (w > 0 ? wsum[w - 1] : 0);
    if (i < N_NODES) {
        g_off[i + 1] = incl;
        g_inv[i] = (v > 0) ? (1.0f / (float)v) : 0.0f;
    }
    if (t == 1023) g_bsum[b] = incl;
}

// finalize offsets; block-local bsum prefix inline (b>>2 const per 256-node block)
__global__ void k_scan3() {
    __shared__ int spre;
    int b = blockIdx.x;
    int t = threadIdx.x;
    int need = b >> 2;
    if (t < 32) {
        int v = (t < need) ? g_bsum[t] : 0;
        if (t + 32 < need) v += g_bsum[t + 32];
        #pragma unroll
        for (int o = 16; o > 0; o >>= 1)
            v += __shfl_xor_sync(0xffffffffu, v, o);
        if (t == 0) spre = v;
    }
    __syncthreads();
    int i = b * 256 + t;
    if (i < N_NODES) {
        int o = g_off[i + 1] + spre;
        g_off[i + 1] = o;
        g_pos[i] = o - g_deg[i];
    }
    if (i == 0) g_off[0] = 0;
}

__global__ void k_scatter(const int* __restrict__ src, const int* __restrict__ dst) {
    int e = blockIdx.x * blockDim.x + threadIdx.x;
    if (e < N_EDGES) {
        int d = dst[e];
        int p = atomicAdd(&g_pos[d], 1);
        g_srcs[p] = src[e];
    }
}

// ------- mean aggregation (128-d fp32 gather); emits mean as bf16 hi/lo planes -------
__global__ void k_agg(const float* __restrict__ h) {
    int w    = (blockIdx.x * blockDim.x + threadIdx.x) >> 5;
    int lane = threadIdx.x & 31;
    if (w >= N_NODES) return;

    int e  = g_off[w];
    int e1 = g_off[w + 1];
    float4 acc = make_float4(0.f, 0.f, 0.f, 0.f);
    const float* base = h + lane * 4;

    for (; e + 3 < e1; e += 4) {
        int s0 = g_srcs[e], s1 = g_srcs[e + 1], s2 = g_srcs[e + 2], s3 = g_srcs[e + 3];
        float4 v0 = *(const float4*)(base + (size_t)s0 * 128);
        float4 v1 = *(const float4*)(base + (size_t)s1 * 128);
        float4 v2 = *(const float4*)(base + (size_t)s2 * 128);
        float4 v3 = *(const float4*)(base + (size_t)s3 * 128);
        acc.x += (v0.x + v1.x) + (v2.x + v3.x);
        acc.y += (v0.y + v1.y) + (v2.y + v3.y);
        acc.z += (v0.z + v1.z) + (v2.z + v3.z);
        acc.w += (v0.w + v1.w) + (v2.w + v3.w);
    }
    for (; e < e1; e++) {
        int s = g_srcs[e];
        float4 v = *(const float4*)(base + (size_t)s * 128);
        acc.x += v.x; acc.y += v.y; acc.z += v.z; acc.w += v.w;
    }

    float inv = g_inv[w];
    float4 o = make_float4(acc.x * inv, acc.y * inv, acc.z * inv, acc.w * inv);
    uint2 hi, lo; split_pack4(o, hi, lo);
    *(uint2*)(g_mh + (size_t)w * 128 + lane * 4) = hi;
    *(uint2*)(g_ml + (size_t)w * 128 + lane * 4) = lo;
}

// ---------------- plane -> smem copies, K=128 chunk ----------------
// A: 128 rows x 128 k. thread t: row = t>>1, k-half = (t&1)*64 (8 uint4 per plane).
__device__ __forceinline__ void load_A_plane(
    __nv_bfloat16* smb, const __nv_bfloat16* __restrict__ ph,
    const __nv_bfloat16* __restrict__ pl, int row0, int t)
{
    int m = t >> 1, kh = (t & 1) * 64;
    int r = row0 + m;
    int off = m * A_STRIDE + kh;
    if (r < N_NODES) {
        const uint4* gh = (const uint4*)(ph + (size_t)r * 128 + kh);
        const uint4* gl = (const uint4*)(pl + (size_t)r * 128 + kh);
        #pragma unroll
        for (int i = 0; i < 8; i++) {
            *(uint4*)(smb + SM_AH + off + i * 8) = gh[i];
            *(uint4*)(smb + SM_AL + off + i * 8) = gl[i];
        }
    } else {
        uint4 z = make_uint4(0, 0, 0, 0);
        #pragma unroll
        for (int i = 0; i < 8; i++) {
            *(uint4*)(smb + SM_AH + off + i * 8) = z;
            *(uint4*)(smb + SM_AL + off + i * 8) = z;
        }
    }
}

// W: 64 rows x 128 k. thread t: row = t>>2, k-quarter = (t&3)*32 (4 uint4 per plane).
__device__ __forceinline__ void load_W_plane(
    __nv_bfloat16* smb, int wrow0, int t)
{
    int j = t >> 2, kh = (t & 3) * 32;
    int off = j * A_STRIDE + kh;
    const uint4* gh = (const uint4*)(g_wh + (size_t)(wrow0 + j) * 128 + kh);
    const uint4* gl = (const uint4*)(g_wl + (size_t)(wrow0 + j) * 128 + kh);
    #pragma unroll
    for (int i = 0; i < 4; i++) {
        *(uint4*)(smb + SM_WH + off + i * 8) = gh[i];
        *(uint4*)(smb + SM_WL + off + i * 8) = gl[i];
    }
}

// one K=128 chunk of bf16x3 mma (8 k-frags)
__device__ __forceinline__ void mma_chunk(
    const __nv_bfloat16* smb, int wm, int wn, int lane, float c[2][4][4])
{
    #pragma unroll
    for (int kf = 0; kf < 8; kf++) {
        int kcol = kf * 16 + (lane & 3) * 2;
        uint32_t ah[2][4], al[2][4];
        #pragma unroll
        for (int mt = 0; mt < 2; mt++) {
            int base = (wm * 32 + mt * 16 + (lane >> 2)) * A_STRIDE + kcol;
            ah[mt][0] = *(const uint32_t*)(smb + SM_AH + base);
            ah[mt][1] = *(const uint32_t*)(smb + SM_AH + base + 8 * A_STRIDE);
            ah[mt][2] = *(const uint32_t*)(smb + SM_AH + base + 8);
            ah[mt][3] = *(const uint32_t*)(smb + SM_AH + base + 8 * A_STRIDE + 8);
            al[mt][0] = *(const uint32_t*)(smb + SM_AL + base);
            al[mt][1] = *(const uint32_t*)(smb + SM_AL + base + 8 * A_STRIDE);
            al[mt][2] = *(const uint32_t*)(smb + SM_AL + base + 8);
            al[mt][3] = *(const uint32_t*)(smb + SM_AL + base + 8 * A_STRIDE + 8);
        }
        uint32_t bh[4][2], bl[4][2];
        #pragma unroll
        for (int nt = 0; nt < 4; nt++) {
            int base = (wn * 32 + nt * 8 + (lane >> 2)) * A_STRIDE + kcol;
            bh[nt][0] = *(const uint32_t*)(smb + SM_WH + base);
            bh[nt][1] = *(const uint32_t*)(smb + SM_WH + base + 8);
            bl[nt][0] = *(const uint32_t*)(smb + SM_WL + base);
            bl[nt][1] = *(const uint32_t*)(smb + SM_WL + base + 8);
        }
        #pragma unroll
        for (int mt = 0; mt < 2; mt++)
            #pragma unroll
            for (int nt = 0; nt < 4; nt++) {
                MMA_BF16(c[mt][nt], ah[mt], bh[nt]);
                MMA_BF16(c[mt][nt], al[mt], bh[nt]);
                MMA_BF16(c[mt][nt], ah[mt], bl[nt]);
            }
    }
}

// ---------- dual GEMM + bias + relu (layers 1 & 2): 2 chunks of K=128 -------
template <bool WRITE_F32>
__global__ __launch_bounds__(256) void k_gemmJ_mma(
    const __nv_bfloat16* __restrict__ mh, const __nv_bfloat16* __restrict__ ml,
    const __nv_bfloat16* __restrict__ rh, const __nv_bfloat16* __restrict__ rl,
    int wl_row, int wr_row, const float* __restrict__ bias,
    float* __restrict__ outf,
    __nv_bfloat16* __restrict__ outh, __nv_bfloat16* __restrict__ outl)
{
    extern __shared__ __nv_bfloat16 smb[];
    const int t    = threadIdx.x;
    const int lane = t & 31;
    const int w    = t >> 5;
    const int wm   = w & 3;
    const int wn   = w >> 2;
    const int row0 = blockIdx.x * 128;
    const int n0   = blockIdx.y * 64;

    float c[2][4][4];
    #pragma unroll
    for (int mt = 0; mt < 2; mt++)
        #pragma unroll
        for (int nt = 0; nt < 4; nt++)
            #pragma unroll
            for (int i = 0; i < 4; i++) c[mt][nt][i] = 0.f;

    #pragma unroll 1
    for (int ph = 0; ph < 2; ph++) {
        const __nv_bfloat16* ahp = ph ? rh : mh;
        const __nv_bfloat16* alp = ph ? rl : ml;
        const int wr0 = (ph ? wr_row : wl_row) + n0;
        load_A_plane(smb, ahp, alp, row0, t);
        load_W_plane(smb, wr0, t);
        __syncthreads();
        mma_chunk(smb, wm, wn, lane, c);
        __syncthreads();
    }

    #pragma unroll
    for (int mt = 0; mt < 2; mt++) {
        int r0 = row0 + wm * 32 + mt * 16 + (lane >> 2);
        #pragma unroll
        for (int nt = 0; nt < 4; nt++) {
            int col = n0 + wn * 32 + nt * 8 + (lane & 3) * 2;
            float b0 = bias[col], b1 = bias[col + 1];
            if (r0 < N_NODES) {
                float f0 = fmaxf(c[mt][nt][0] + b0, 0.f);
                float f1 = fmaxf(c[mt][nt][1] + b1, 0.f);
                if (WRITE_F32)
                    *(float2*)(outf + (size_t)r0 * 128 + col) = make_float2(f0, f1);
                uint32_t hi, lo; split2(f0, f1, hi, lo);
                *(uint32_t*)(outh + (size_t)r0 * 128 + col) = hi;
                *(uint32_t*)(outl + (size_t)r0 * 128 + col) = lo;
            }
            if (r0 + 8 < N_NODES) {
                float f2 = fmaxf(c[mt][nt][2] + b0, 0.f);
                float f3 = fmaxf(c[mt][nt][3] + b1, 0.f);
                if (WRITE_F32)
                    *(float2*)(outf + (size_t)(r0 + 8) * 128 + col) = make_float2(f2, f3);
                uint32_t hi, lo; split2(f2, f3, hi, lo);
                *(uint32_t*)(outh + (size_t)(r0 + 8) * 128 + col) = hi;
                *(uint32_t*)(outl + (size_t)(r0 + 8) * 128 + col) = lo;
            }
        }
    }
}

// ---------- layer-3 pair GEMM: p = h2@Wl3^T, q = h2@Wr3^T + b (1 chunk K=128) ------
__global__ __launch_bounds__(256) void k_gemm3_mma(
    const __nv_bfloat16* __restrict__ ah, const __nv_bfloat16* __restrict__ al,
    const float* __restrict__ bias,
    float* __restrict__ p, float* __restrict__ q)
{
    extern __shared__ __nv_bfloat16 smb[];
    const int t    = threadIdx.x;
    const int lane = t & 31;
    const int w    = t >> 5;
    const int wm   = w & 3;
    const int wn   = w >> 2;      // 0 -> p, 1 -> q
    const int row0 = blockIdx.x * 128;

    float c[2][4][4];
    #pragma unroll
    for (int mt = 0; mt < 2; mt++)
        #pragma unroll
        for (int nt = 0; nt < 4; nt++)
            #pragma unroll
            for (int i = 0; i < 4; i++) c[mt][nt][i] = 0.f;

    load_A_plane(smb, ah, al, row0, t);
    load_W_plane(smb, 512, t);
    __syncthreads();
    mma_chunk(smb, wm, wn, lane, c);

    float* dstm = (wn == 0) ? p : q;
    #pragma unroll
    for (int mt = 0; mt < 2; mt++) {
        int r0 = row0 + wm * 32 + mt * 16 + (lane >> 2);
        #pragma unroll
        for (int nt = 0; nt < 4; nt++) {
            int col = nt * 8 + (lane & 3) * 2;
            float b0 = (wn == 1) ? bias[col]     : 0.f;
            float b1 = (wn == 1) ? bias[col + 1] : 0.f;
            if (r0 < N_NODES)
                *(float2*)(dstm + (size_t)r0 * 32 + col) =
                    make_float2(c[mt][nt][0] + b0, c[mt][nt][1] + b1);
            if (r0 + 8 < N_NODES)
                *(float2*)(dstm + (size_t)(r0 + 8) * 32 + col) =
                    make_float2(c[mt][nt][2] + b0, c[mt][nt][3] + b1);
        }
    }
}

// ---------------- layer-3 aggregation in 32-d + final relu ----------------
__global__ void k_agg3(const float* __restrict__ p, const float* __restrict__ q,
                       float* __restrict__ out) {
    int w    = (blockIdx.x * blockDim.x + threadIdx.x) >> 5;
    int lane = threadIdx.x & 31;
    if (w >= N_NODES) return;

    int e  = g_off[w];
    int e1 = g_off[w + 1];
    float acc = 0.f;
    for (; e + 3 < e1; e += 4) {
        int s0 = g_srcs[e], s1 = g_srcs[e + 1], s2 = g_srcs[e + 2], s3 = g_srcs[e + 3];
        acc += (p[(size_t)s0 * 32 + lane] + p[(size_t)s1 * 32 + lane])
             + (p[(size_t)s2 * 32 + lane] + p[(size_t)s3 * 32 + lane]);
    }
    for (; e < e1; e++) acc += p[(size_t)g_srcs[e] * 32 + lane];

    out[(size_t)w * 32 + lane] = fmaxf(acc * g_inv[w] + q[(size_t)w * 32 + lane], 0.f);
}

// ---------------- launch ----------------
extern "C" void kernel_launch(void* const* d_in, const int* in_sizes, int n_in,
                              void* d_out, int out_size) {
    const float* x   = (const float*)d_in[0];
    const int*   ei  = (const int*)d_in[1];
    const float* Wl1 = (const float*)d_in[2];
    const float* bl1 = (const float*)d_in[3];
    const float* Wr1 = (const float*)d_in[4];
    const float* Wl2 = (const float*)d_in[5];
    const float* bl2 = (const float*)d_in[6];
    const float* Wr2 = (const float*)d_in[7];
    const float* Wl3 = (const float*)d_in[8];
    const float* bl3 = (const float*)d_in[9];
    const float* Wr3 = (const float*)d_in[10];
    float* out = (float*)d_out;

    const int* src = ei;
    const int* dst = ei + N_EDGES;

    cudaFuncSetAttribute(k_gemmJ_mma<true>,  cudaFuncAttributeMaxDynamicSharedMemorySize, SMEM_MMA);
    cudaFuncSetAttribute(k_gemmJ_mma<false>, cudaFuncAttributeMaxDynamicSharedMemorySize, SMEM_MMA);
    cudaFuncSetAttribute(k_gemm3_mma,        cudaFuncAttributeMaxDynamicSharedMemorySize, SMEM_MMA);

    int* deg_p;
    float *h1_p, *p_p, *q_p;
    __nv_bfloat16 *xh_p, *xl_p, *mh_p, *ml_p, *h1h_p, *h1l_p, *h2h_p, *h2l_p;
    cudaGetSymbolAddress((void**)&deg_p, g_deg);
    cudaGetSymbolAddress((void**)&h1_p,  g_h1);
    cudaGetSymbolAddress((void**)&p_p,   g_p);
    cudaGetSymbolAddress((void**)&q_p,   g_q);
    cudaGetSymbolAddress((void**)&xh_p,  g_xh);
    cudaGetSymbolAddress((void**)&xl_p,  g_xl);
    cudaGetSymbolAddress((void**)&mh_p,  g_mh);
    cudaGetSymbolAddress((void**)&ml_p,  g_ml);
    cudaGetSymbolAddress((void**)&h1h_p, g_h1h);
    cudaGetSymbolAddress((void**)&h1l_p, g_h1l);
    cudaGetSymbolAddress((void**)&h2h_p, g_h2h);
    cudaGetSymbolAddress((void**)&h2l_p, g_h2l);

    const int AB = (N_NODES * 32 + 255) / 256;
    const int FB = (X4 + W4 + 255) / 256;      // covers N_EDGES too
    dim3 GJ((N_NODES + 127) / 128, 2);
    const int G3 = (N_NODES + 127) / 128;

    // CSR build + operand split
    cudaMemsetAsync(deg_p, 0, N_NODES * sizeof(int));
    k_split_count<<<FB, 256>>>(x, Wl1, Wr1, Wl2, Wr2, Wl3, Wr3, dst);
    k_scan1<<<SCAN_B, 1024>>>();
    k_scan3<<<(N_NODES + 255) / 256, 256>>>();
    k_scatter<<<(N_EDGES + 255) / 256, 256>>>(src, dst);

    // layer 1
    k_agg<<<AB, 256>>>(x);
    k_gemmJ_mma<true><<<GJ, 256, SMEM_MMA>>>(mh_p, ml_p, xh_p, xl_p, 0, 128, bl1,
                                             h1_p, h1h_p, h1l_p);
    // layer 2
    k_agg<<<AB, 256>>>(h1_p);
    k_gemmJ_mma<false><<<GJ, 256, SMEM_MMA>>>(mh_p, ml_p, h1h_p, h1l_p, 256, 384, bl2,
                                              nullptr, h2h_p, h2l_p);
    // layer 3
    k_gemm3_mma<<<G3, 256, SMEM_MMA>>>(h2h_p, h2l_p, bl3, p_p, q_p);
    k_agg3<<<AB, 256>>>(p_p, q_p, out);
}

// round 15
// speedup vs baseline: 1.3192x; 1.3192x over previous
#include <cuda_runtime.h>
#include <cuda_bf16.h>
#include <cstdint>

#define N_NODES 50000
#define N_EDGES 800000
#define SCAN_B  49   // ceil(50000/1024)

// ---------------- scratch (static __device__ globals; no allocation) ----------------
__device__ int   g_deg [N_NODES];
__device__ int   g_off [N_NODES + 1];
__device__ int   g_pos [N_NODES];
__device__ int   g_srcs[N_EDGES];
__device__ float g_inv [N_NODES];
__device__ int   g_bsum[64];

__device__ float g_h1 [(size_t)N_NODES * 128];   // fp32 (gathered by layer-2 agg)
__device__ float g_p  [(size_t)N_NODES * 32];
__device__ float g_q  [(size_t)N_NODES * 32];

// bf16 hi/lo planes (pre-split operands for mma GEMMs)
__device__ __align__(16) __nv_bfloat16 g_xh [(size_t)N_NODES * 128];
__device__ __align__(16) __nv_bfloat16 g_xl [(size_t)N_NODES * 128];
__device__ __align__(16) __nv_bfloat16 g_mh [(size_t)N_NODES * 128];
__device__ __align__(16) __nv_bfloat16 g_ml [(size_t)N_NODES * 128];
__device__ __align__(16) __nv_bfloat16 g_h1h[(size_t)N_NODES * 128];
__device__ __align__(16) __nv_bfloat16 g_h1l[(size_t)N_NODES * 128];
__device__ __align__(16) __nv_bfloat16 g_h2h[(size_t)N_NODES * 128];
__device__ __align__(16) __nv_bfloat16 g_h2l[(size_t)N_NODES * 128];
// packed W planes: [0,128)=Wl1 [128,256)=Wr1 [256,384)=Wl2 [384,512)=Wr2 [512,544)=Wl3 [544,576)=Wr3
#define WROWS 576
__device__ __align__(16) __nv_bfloat16 g_wh[WROWS * 128];
__device__ __align__(16) __nv_bfloat16 g_wl[WROWS * 128];

// ---------------- helpers ----------------
#define MMA_BF16(c, a, b) \
    asm volatile("mma.sync.aligned.m16n8k16.row.col.f32.bf16.bf16.f32 " \
        "{%0,%1,%2,%3}, {%4,%5,%6,%7}, {%8,%9}, {%0,%1,%2,%3};" \
        : "+f"((c)[0]), "+f"((c)[1]), "+f"((c)[2]), "+f"((c)[3]) \
        : "r"((a)[0]), "r"((a)[1]), "r"((a)[2]), "r"((a)[3]), \
          "r"((b)[0]), "r"((b)[1]))

__device__ __forceinline__ uint32_t pack_bf2(float a, float b) {
    __nv_bfloat162 h = __floats2bfloat162_rn(a, b);
    return *reinterpret_cast<uint32_t*>(&h);
}
__device__ __forceinline__ void split_pack4(float4 v, uint2& hi, uint2& lo) {
    float hx = __bfloat162float(__float2bfloat16(v.x));
    float hy = __bfloat162float(__float2bfloat16(v.y));
    float hz = __bfloat162float(__float2bfloat16(v.z));
    float hw = __bfloat162float(__float2bfloat16(v.w));
    hi = make_uint2(pack_bf2(hx, hy), pack_bf2(hz, hw));
    lo = make_uint2(pack_bf2(v.x - hx, v.y - hy), pack_bf2(v.z - hz, v.w - hw));
}
__device__ __forceinline__ void split2(float f0, float f1, uint32_t& hi, uint32_t& lo) {
    float h0 = __bfloat162float(__float2bfloat16(f0));
    float h1 = __bfloat162float(__float2bfloat16(f1));
    hi = pack_bf2(h0, h1);
    lo = pack_bf2(f0 - h0, f1 - h1);
}

// smem layout (bf16 elements), row stride 72 (144B, conflict-free frags)
#define A_STRIDE 72
#define SM_AH 0
#define SM_AL 9216       // 128*72
#define SM_WH 18432
#define SM_WL 23040
#define SMEM_MMA ((23040 + 4608) * 2)   // 55296 bytes

// ---------------- fused split(x,W) + degree count ----------------
#define X4 1600000          // 50000*128/4
#define W4 18432            // 576*128/4
__global__ void k_split_count(const float* __restrict__ x,
                              const float* __restrict__ Wl1, const float* __restrict__ Wr1,
                              const float* __restrict__ Wl2, const float* __restrict__ Wr2,
                              const float* __restrict__ Wl3, const float* __restrict__ Wr3,
                              const int* __restrict__ dst) {
    int i = blockIdx.x * blockDim.x + threadIdx.x;
    if (i < N_EDGES) atomicAdd(&g_deg[dst[i]], 1);
    if (i < X4) {
        float4 v = *(const float4*)(x + (size_t)i * 4);
        uint2 hi, lo; split_pack4(v, hi, lo);
        *(uint2*)(g_xh + (size_t)i * 4) = hi;
        *(uint2*)(g_xl + (size_t)i * 4) = lo;
    } else if (i < X4 + W4) {
        int wi = i - X4;
        int row = wi >> 5, c4 = wi & 31;
        const float* src;
        if      (row < 128) src = Wl1 + (size_t)row * 128;
        else if (row < 256) src = Wr1 + (size_t)(row - 128) * 128;
        else if (row < 384) src = Wl2 + (size_t)(row - 256) * 128;
        else if (row < 512) src = Wr2 + (size_t)(row - 384) * 128;
        else if (row < 544) src = Wl3 + (size_t)(row - 512) * 128;
        else                src = Wr3 + (size_t)(row - 544) * 128;
        float4 v = *(const float4*)(src + c4 * 4);
        uint2 hi, lo; split_pack4(v, hi, lo);
        *(uint2*)(g_wh + row * 128 + c4 * 4) = hi;
        *(uint2*)(g_wl + row * 128 + c4 * 4) = lo;
    }
}

// ---------------- CSR scan ----------------
__global__ void k_scan1() {
    __shared__ int wsum[32];
    int t = threadIdx.x, b = blockIdx.x;
    int i = b * 1024 + t;
    int v = (i < N_NODES) ? g_deg[i] : 0;
    int lane = t & 31, w = t >> 5;
    int x = v;
    #pragma unroll
    for (int o = 1; o < 32; o <<= 1) {
        int y = __shfl_up_sync(0xffffffffu, x, o);
        if (lane >= o) x += y;
    }
    if (lane == 31) wsum[w] = x;
    __syncthreads();
    if (w == 0) {
        int s = wsum[lane];
        #pragma unroll
        for (int o = 1; o < 32; o <<= 1) {
            int y = __shfl_up_sync(0xffffffffu, s, o);
            if (lane >= o) s += y;
        }
        wsum[lane] = s;
    }
    __syncthreads();
    int incl = x + (w > 0 ? wsum[w - 1] : 0);
    if (i < N_NODES) {
        g_off[i + 1] = incl;
        g_inv[i] = (v > 0) ? (1.0f / (float)v) : 0.0f;
    }
    if (t == 1023) g_bsum[b] = incl;
}

// finalize offsets; block-local bsum prefix inline (b>>2 const per 256-node block)
__global__ void k_scan3() {
    __shared__ int spre;
    int b = blockIdx.x;
    int t = threadIdx.x;
    int need = b >> 2;
    if (t < 32) {
        int v = (t < need) ? g_bsum[t] : 0;
        if (t + 32 < need) v += g_bsum[t + 32];
        #pragma unroll
        for (int o = 16; o > 0; o >>= 1)
            v += __shfl_xor_sync(0xffffffffu, v, o);
        if (t == 0) spre = v;
    }
    __syncthreads();
    int i = b * 256 + t;
    if (i < N_NODES) {
        int o = g_off[i + 1] + spre;
        g_off[i + 1] = o;
        g_pos[i] = o - g_deg[i];
    }
    if (i == 0) g_off[0] = 0;
}

__global__ void k_scatter(const int* __restrict__ src, const int* __restrict__ dst) {
    int e = blockIdx.x * blockDim.x + threadIdx.x;
    if (e < N_EDGES) {
        int d = dst[e];
        int p = atomicAdd(&g_pos[d], 1);
        g_srcs[p] = src[e];
    }
}

// ------- mean aggregation (128-d fp32 gather); emits mean as bf16 hi/lo planes -------
__global__ void k_agg(const float* __restrict__ h) {
    int w    = (blockIdx.x * blockDim.x + threadIdx.x) >> 5;
    int lane = threadIdx.x & 31;
    if (w >= N_NODES) return;

    int e  = g_off[w];
    int e1 = g_off[w + 1];
    float4 acc = make_float4(0.f, 0.f, 0.f, 0.f);
    const float* base = h + lane * 4;

    for (; e + 3 < e1; e += 4) {
        int s0 = g_srcs[e], s1 = g_srcs[e + 1], s2 = g_srcs[e + 2], s3 = g_srcs[e + 3];
        float4 v0 = *(const float4*)(base + (size_t)s0 * 128);
        float4 v1 = *(const float4*)(base + (size_t)s1 * 128);
        float4 v2 = *(const float4*)(base + (size_t)s2 * 128);
        float4 v3 = *(const float4*)(base + (size_t)s3 * 128);
        acc.x += (v0.x + v1.x) + (v2.x + v3.x);
        acc.y += (v0.y + v1.y) + (v2.y + v3.y);
        acc.z += (v0.z + v1.z) + (v2.z + v3.z);
        acc.w += (v0.w + v1.w) + (v2.w + v3.w);
    }
    for (; e < e1; e++) {
        int s = g_srcs[e];
        float4 v = *(const float4*)(base + (size_t)s * 128);
        acc.x += v.x; acc.y += v.y; acc.z += v.z; acc.w += v.w;
    }

    float inv = g_inv[w];
    float4 o = make_float4(acc.x * inv, acc.y * inv, acc.z * inv, acc.w * inv);
    uint2 hi, lo; split_pack4(o, hi, lo);
    *(uint2*)(g_mh + (size_t)w * 128 + lane * 4) = hi;
    *(uint2*)(g_ml + (size_t)w * 128 + lane * 4) = lo;
}

// ---------------- plane -> smem copies (synchronous, proven) ----------------
__device__ __forceinline__ void load_A_plane(
    __nv_bfloat16* smb, const __nv_bfloat16* __restrict__ ph,
    const __nv_bfloat16* __restrict__ pl, int row0, int kc, int t)
{
    int m = t >> 1, kh = (t & 1) * 32;
    int r = row0 + m;
    int off = m * A_STRIDE + kh;
    if (r < N_NODES) {
        const uint4* gh = (const uint4*)(ph + (size_t)r * 128 + kc + kh);
        const uint4* gl = (const uint4*)(pl + (size_t)r * 128 + kc + kh);
        #pragma unroll
        for (int i = 0; i < 4; i++) {
            *(uint4*)(smb + SM_AH + off + i * 8) = gh[i];
            *(uint4*)(smb + SM_AL + off + i * 8) = gl[i];
        }
    } else {
        uint4 z = make_uint4(0, 0, 0, 0);
        #pragma unroll
        for (int i = 0; i < 4; i++) {
            *(uint4*)(smb + SM_AH + off + i * 8) = z;
            *(uint4*)(smb + SM_AL + off + i * 8) = z;
        }
    }
}

__device__ __forceinline__ void load_W_plane(
    __nv_bfloat16* smb, int wrow0, int kc, int t)
{
    int j = t >> 2, kh = (t & 3) * 16;
    int off = j * A_STRIDE + kh;
    const uint4* gh = (const uint4*)(g_wh + (size_t)(wrow0 + j) * 128 + kc + kh);
    const uint4* gl = (const uint4*)(g_wl + (size_t)(wrow0 + j) * 128 + kc + kh);
    #pragma unroll
    for (int i = 0; i < 2; i++) {
        *(uint4*)(smb + SM_WH + off + i * 8) = gh[i];
        *(uint4*)(smb + SM_WL + off + i * 8) = gl[i];
    }
}

// one K=64 chunk of bf16x3 mma
__device__ __forceinline__ void mma_chunk(
    const __nv_bfloat16* smb, int wm, int wn, int lane, float c[2][4][4])
{
    #pragma unroll
    for (int kf = 0; kf < 4; kf++) {
        int kcol = kf * 16 + (lane & 3) * 2;
        uint32_t ah[2][4], al[2][4];
        #pragma unroll
        for (int mt = 0; mt < 2; mt++) {
            int base = (wm * 32 + mt * 16 + (lane >> 2)) * A_STRIDE + kcol;
            ah[mt][0] = *(const uint32_t*)(smb + SM_AH + base);
            ah[mt][1] = *(const uint32_t*)(smb + SM_AH + base + 8 * A_STRIDE);
            ah[mt][2] = *(const uint32_t*)(smb + SM_AH + base + 8);
            ah[mt][3] = *(const uint32_t*)(smb + SM_AH + base + 8 * A_STRIDE + 8);
            al[mt][0] = *(const uint32_t*)(smb + SM_AL + base);
            al[mt][1] = *(const uint32_t*)(smb + SM_AL + base + 8 * A_STRIDE);
            al[mt][2] = *(const uint32_t*)(smb + SM_AL + base + 8);
            al[mt][3] = *(const uint32_t*)(smb + SM_AL + base + 8 * A_STRIDE + 8);
        }
        uint32_t bh[4][2], bl[4][2];
        #pragma unroll
        for (int nt = 0; nt < 4; nt++) {
            int base = (wn * 32 + nt * 8 + (lane >> 2)) * A_STRIDE + kcol;
            bh[nt][0] = *(const uint32_t*)(smb + SM_WH + base);
            bh[nt][1] = *(const uint32_t*)(smb + SM_WH + base + 8);
            bl[nt][0] = *(const uint32_t*)(smb + SM_WL + base);
            bl[nt][1] = *(const uint32_t*)(smb + SM_WL + base + 8);
        }
        #pragma unroll
        for (int mt = 0; mt < 2; mt++)
            #pragma unroll
            for (int nt = 0; nt < 4; nt++) {
                MMA_BF16(c[mt][nt], ah[mt], bh[nt]);
                MMA_BF16(c[mt][nt], al[mt], bh[nt]);
                MMA_BF16(c[mt][nt], ah[mt], bl[nt]);
            }
    }
}

// ---------- dual GEMM + bias + relu (layers 1 & 2), synchronous loads -------
template <bool WRITE_F32>
__global__ __launch_bounds__(256) void k_gemmJ_mma(
    const __nv_bfloat16* __restrict__ mh, const __nv_bfloat16* __restrict__ ml,
    const __nv_bfloat16* __restrict__ rh, const __nv_bfloat16* __restrict__ rl,
    int wl_row, int wr_row, const float* __restrict__ bias,
    float* __restrict__ outf,
    __nv_bfloat16* __restrict__ outh, __nv_bfloat16* __restrict__ outl)
{
    extern __shared__ __nv_bfloat16 smb[];
    const int t    = threadIdx.x;
    const int lane = t & 31;
    const int w    = t >> 5;
    const int wm   = w & 3;
    const int wn   = w >> 2;
    const int row0 = blockIdx.x * 128;
    const int n0   = blockIdx.y * 64;

    float c[2][4][4];
    #pragma unroll
    for (int mt = 0; mt < 2; mt++)
        #pragma unroll
        for (int nt = 0; nt < 4; nt++)
            #pragma unroll
            for (int i = 0; i < 4; i++) c[mt][nt][i] = 0.f;

    #pragma unroll 1
    for (int ph = 0; ph < 2; ph++) {
        const __nv_bfloat16* ahp = ph ? rh : mh;
        const __nv_bfloat16* alp = ph ? rl : ml;
        const int wr0 = (ph ? wr_row : wl_row) + n0;
        #pragma unroll 1
        for (int ck = 0; ck < 2; ck++) {
            const int kc = ck * 64;
            load_A_plane(smb, ahp, alp, row0, kc, t);
            load_W_plane(smb, wr0, kc, t);
            __syncthreads();
            mma_chunk(smb, wm, wn, lane, c);
            __syncthreads();
        }
    }

    #pragma unroll
    for (int mt = 0; mt < 2; mt++) {
        int r0 = row0 + wm * 32 + mt * 16 + (lane >> 2);
        #pragma unroll
        for (int nt = 0; nt < 4; nt++) {
            int col = n0 + wn * 32 + nt * 8 + (lane & 3) * 2;
            float b0 = bias[col], b1 = bias[col + 1];
            if (r0 < N_NODES) {
                float f0 = fmaxf(c[mt][nt][0] + b0, 0.f);
                float f1 = fmaxf(c[mt][nt][1] + b1, 0.f);
                if (WRITE_F32)
                    *(float2*)(outf + (size_t)r0 * 128 + col) = make_float2(f0, f1);
                uint32_t hi, lo; split2(f0, f1, hi, lo);
                *(uint32_t*)(outh + (size_t)r0 * 128 + col) = hi;
                *(uint32_t*)(outl + (size_t)r0 * 128 + col) = lo;
            }
            if (r0 + 8 < N_NODES) {
                float f2 = fmaxf(c[mt][nt][2] + b0, 0.f);
                float f3 = fmaxf(c[mt][nt][3] + b1, 0.f);
                if (WRITE_F32)
                    *(float2*)(outf + (size_t)(r0 + 8) * 128 + col) = make_float2(f2, f3);
                uint32_t hi, lo; split2(f2, f3, hi, lo);
                *(uint32_t*)(outh + (size_t)(r0 + 8) * 128 + col) = hi;
                *(uint32_t*)(outl + (size_t)(r0 + 8) * 128 + col) = lo;
            }
        }
    }
}

// ---------- layer-3 pair GEMM: p = h2@Wl3^T, q = h2@Wr3^T + b ----------
__global__ __launch_bounds__(256) void k_gemm3_mma(
    const __nv_bfloat16* __restrict__ ah, const __nv_bfloat16* __restrict__ al,
    const float* __restrict__ bias,
    float* __restrict__ p, float* __restrict__ q)
{
    extern __shared__ __nv_bfloat16 smb[];
    const int t    = threadIdx.x;
    const int lane = t & 31;
    const int w    = t >> 5;
    const int wm   = w & 3;
    const int wn   = w >> 2;      // 0 -> p, 1 -> q
    const int row0 = blockIdx.x * 128;

    float c[2][4][4];
    #pragma unroll
    for (int mt = 0; mt < 2; mt++)
        #pragma unroll
        for (int nt = 0; nt < 4; nt++)
            #pragma unroll
            for (int i = 0; i < 4; i++) c[mt][nt][i] = 0.f;

    #pragma unroll 1
    for (int ck = 0; ck < 2; ck++) {
        const int kc = ck * 64;
        load_A_plane(smb, ah, al, row0, kc, t);
        load_W_plane(smb, 512, kc, t);
        __syncthreads();
        mma_chunk(smb, wm, wn, lane, c);
        __syncthreads();
    }

    float* dstm = (wn == 0) ? p : q;
    #pragma unroll
    for (int mt = 0; mt < 2; mt++) {
        int r0 = row0 + wm * 32 + mt * 16 + (lane >> 2);
        #pragma unroll
        for (int nt = 0; nt < 4; nt++) {
            int col = nt * 8 + (lane & 3) * 2;
            float b0 = (wn == 1) ? bias[col]     : 0.f;
            float b1 = (wn == 1) ? bias[col + 1] : 0.f;
            if (r0 < N_NODES)
                *(float2*)(dstm + (size_t)r0 * 32 + col) =
                    make_float2(c[mt][nt][0] + b0, c[mt][nt][1] + b1);
            if (r0 + 8 < N_NODES)
                *(float2*)(dstm + (size_t)(r0 + 8) * 32 + col) =
                    make_float2(c[mt][nt][2] + b0, c[mt][nt][3] + b1);
        }
    }
}

// ---------------- layer-3 aggregation in 32-d + final relu ----------------
__global__ void k_agg3(const float* __restrict__ p, const float* __restrict__ q,
                       float* __restrict__ out) {
    int w    = (blockIdx.x * blockDim.x + threadIdx.x) >> 5;
    int lane = threadIdx.x & 31;
    if (w >= N_NODES) return;

    int e  = g_off[w];
    int e1 = g_off[w + 1];
    float acc = 0.f;
    for (; e + 3 < e1; e += 4) {
        int s0 = g_srcs[e], s1 = g_srcs[e + 1], s2 = g_srcs[e + 2], s3 = g_srcs[e + 3];
        acc += (p[(size_t)s0 * 32 + lane] + p[(size_t)s1 * 32 + lane])
             + (p[(size_t)s2 * 32 + lane] + p[(size_t)s3 * 32 + lane]);
    }
    for (; e < e1; e++) acc += p[(size_t)g_srcs[e] * 32 + lane];

    out[(size_t)w * 32 + lane] = fmaxf(acc * g_inv[w] + q[(size_t)w * 32 + lane], 0.f);
}

// ---------------- launch ----------------
extern "C" void kernel_launch(void* const* d_in, const int* in_sizes, int n_in,
                              void* d_out, int out_size) {
    const float* x   = (const float*)d_in[0];
    const int*   ei  = (const int*)d_in[1];
    const float* Wl1 = (const float*)d_in[2];
    const float* bl1 = (const float*)d_in[3];
    const float* Wr1 = (const float*)d_in[4];
    const float* Wl2 = (const float*)d_in[5];
    const float* bl2 = (const float*)d_in[6];
    const float* Wr2 = (const float*)d_in[7];
    const float* Wl3 = (const float*)d_in[8];
    const float* bl3 = (const float*)d_in[9];
    const float* Wr3 = (const float*)d_in[10];
    float* out = (float*)d_out;

    const int* src = ei;
    const int* dst = ei + N_EDGES;

    cudaFuncSetAttribute(k_gemmJ_mma<true>,  cudaFuncAttributeMaxDynamicSharedMemorySize, SMEM_MMA);
    cudaFuncSetAttribute(k_gemmJ_mma<false>, cudaFuncAttributeMaxDynamicSharedMemorySize, SMEM_MMA);
    cudaFuncSetAttribute(k_gemm3_mma,        cudaFuncAttributeMaxDynamicSharedMemorySize, SMEM_MMA);

    int* deg_p;
    float *h1_p, *p_p, *q_p;
    __nv_bfloat16 *xh_p, *xl_p, *mh_p, *ml_p, *h1h_p, *h1l_p, *h2h_p, *h2l_p;
    cudaGetSymbolAddress((void**)&deg_p, g_deg);
    cudaGetSymbolAddress((void**)&h1_p,  g_h1);
    cudaGetSymbolAddress((void**)&p_p,   g_p);
    cudaGetSymbolAddress((void**)&q_p,   g_q);
    cudaGetSymbolAddress((void**)&xh_p,  g_xh);
    cudaGetSymbolAddress((void**)&xl_p,  g_xl);
    cudaGetSymbolAddress((void**)&mh_p,  g_mh);
    cudaGetSymbolAddress((void**)&ml_p,  g_ml);
    cudaGetSymbolAddress((void**)&h1h_p, g_h1h);
    cudaGetSymbolAddress((void**)&h1l_p, g_h1l);
    cudaGetSymbolAddress((void**)&h2h_p, g_h2h);
    cudaGetSymbolAddress((void**)&h2l_p, g_h2l);

    const int AB = (N_NODES * 32 + 255) / 256;
    const int FB = (X4 + W4 + 255) / 256;      // covers N_EDGES too
    dim3 GJ((N_NODES + 127) / 128, 2);
    const int G3 = (N_NODES + 127) / 128;

    // CSR build + operand split
    cudaMemsetAsync(deg_p, 0, N_NODES * sizeof(int));
    k_split_count<<<FB, 256>>>(x, Wl1, Wr1, Wl2, Wr2, Wl3, Wr3, dst);
    k_scan1<<<SCAN_B, 1024>>>();
    k_scan3<<<(N_NODES + 255) / 256, 256>>>();
    k_scatter<<<(N_EDGES + 255) / 256, 256>>>(src, dst);

    // layer 1
    k_agg<<<AB, 256>>>(x);
    k_gemmJ_mma<true><<<GJ, 256, SMEM_MMA>>>(mh_p, ml_p, xh_p, xl_p, 0, 128, bl1,
                                             h1_p, h1h_p, h1l_p);
    // layer 2
    k_agg<<<AB, 256>>>(h1_p);
    k_gemmJ_mma<false><<<GJ, 256, SMEM_MMA>>>(mh_p, ml_p, h1h_p, h1l_p, 256, 384, bl2,
                                              nullptr, h2h_p, h2l_p);
    // layer 3
    k_gemm3_mma<<<G3, 256, SMEM_MMA>>>(h2h_p, h2l_p, bl3, p_p, q_p);
    k_agg3<<<AB, 256>>>(p_p, q_p, out);
}

// round 17
// speedup vs baseline: 1.3913x; 1.0546x over previous
#include <cuda_runtime.h>
#include <cuda_bf16.h>
#include <cstdint>

#define N_NODES 50000
#define N_EDGES 800000
#define SCAN_B  49   // ceil(50000/1024)

// ---------------- scratch (static __device__ globals; no allocation) ----------------
__device__ int   g_deg [N_NODES];
__device__ int   g_off [N_NODES + 1];
__device__ int   g_pos [N_NODES];
__device__ int   g_srcs[N_EDGES];
__device__ float g_inv [N_NODES];
__device__ int   g_bsum[64];

__device__ float g_p  [(size_t)N_NODES * 32];
__device__ float g_q  [(size_t)N_NODES * 32];

// bf16 hi/lo planes (pre-split operands for mma GEMMs)
__device__ __align__(16) __nv_bfloat16 g_xh [(size_t)N_NODES * 128];
__device__ __align__(16) __nv_bfloat16 g_xl [(size_t)N_NODES * 128];
__device__ __align__(16) __nv_bfloat16 g_mh [(size_t)N_NODES * 128];
__device__ __align__(16) __nv_bfloat16 g_ml [(size_t)N_NODES * 128];
__device__ __align__(16) __nv_bfloat16 g_h1h[(size_t)N_NODES * 128];
__device__ __align__(16) __nv_bfloat16 g_h1l[(size_t)N_NODES * 128];
__device__ __align__(16) __nv_bfloat16 g_h2h[(size_t)N_NODES * 128];
__device__ __align__(16) __nv_bfloat16 g_h2l[(size_t)N_NODES * 128];
// packed W planes: [0,128)=Wl1 [128,256)=Wr1 [256,384)=Wl2 [384,512)=Wr2 [512,544)=Wl3 [544,576)=Wr3
#define WROWS 576
__device__ __align__(16) __nv_bfloat16 g_wh[WROWS * 128];
__device__ __align__(16) __nv_bfloat16 g_wl[WROWS * 128];

// ---------------- helpers ----------------
#define MMA_BF16(c, a, b) \
    asm volatile("mma.sync.aligned.m16n8k16.row.col.f32.bf16.bf16.f32 " \
        "{%0,%1,%2,%3}, {%4,%5,%6,%7}, {%8,%9}, {%0,%1,%2,%3};" \
        : "+f"((c)[0]), "+f"((c)[1]), "+f"((c)[2]), "+f"((c)[3]) \
        : "r"((a)[0]), "r"((a)[1]), "r"((a)[2]), "r"((a)[3]), \
          "r"((b)[0]), "r"((b)[1]))

__device__ __forceinline__ uint32_t pack_bf2(float a, float b) {
    __nv_bfloat162 h = __floats2bfloat162_rn(a, b);
    return *reinterpret_cast<uint32_t*>(&h);
}
__device__ __forceinline__ void split_pack4(float4 v, uint2& hi, uint2& lo) {
    float hx = __bfloat162float(__float2bfloat16(v.x));
    float hy = __bfloat162float(__float2bfloat16(v.y));
    float hz = __bfloat162float(__float2bfloat16(v.z));
    float hw = __bfloat162float(__float2bfloat16(v.w));
    hi = make_uint2(pack_bf2(hx, hy), pack_bf2(hz, hw));
    lo = make_uint2(pack_bf2(v.x - hx, v.y - hy), pack_bf2(v.z - hz, v.w - hw));
}
__device__ __forceinline__ void split2(float f0, float f1, uint32_t& hi, uint32_t& lo) {
    float h0 = __bfloat162float(__float2bfloat16(f0));
    float h1 = __bfloat162float(__float2bfloat16(f1));
    hi = pack_bf2(h0, h1);
    lo = pack_bf2(f0 - h0, f1 - h1);
}
// 4 bf16 (hi plane only) -> 4 fp32
__device__ __forceinline__ float4 bf4_to_f4(uint2 u) {
    float2 a = __bfloat1622float2(*reinterpret_cast<__nv_bfloat162*>(&u.x));
    float2 b = __bfloat1622float2(*reinterpret_cast<__nv_bfloat162*>(&u.y));
    return make_float4(a.x, a.y, b.x, b.y);
}

// smem layout (bf16 elements), row stride 72 (144B, conflict-free frags)
#define A_STRIDE 72
#define SM_AH 0
#define SM_AL 9216       // 128*72
#define SM_WH 18432
#define SM_WL 23040
#define SMEM_MMA ((23040 + 4608) * 2)   // 55296 bytes

// ---------------- fused split(x,W) + degree count ----------------
#define X4 1600000          // 50000*128/4
#define W4 18432            // 576*128/4
__global__ void k_split_count(const float* __restrict__ x,
                              const float* __restrict__ Wl1, const float* __restrict__ Wr1,
                              const float* __restrict__ Wl2, const float* __restrict__ Wr2,
                              const float* __restrict__ Wl3, const float* __restrict__ Wr3,
                              const int* __restrict__ dst) {
    int i = blockIdx.x * blockDim.x + threadIdx.x;
    if (i < N_EDGES) atomicAdd(&g_deg[dst[i]], 1);
    if (i < X4) {
        float4 v = *(const float4*)(x + (size_t)i * 4);
        uint2 hi, lo; split_pack4(v, hi, lo);
        *(uint2*)(g_xh + (size_t)i * 4) = hi;
        *(uint2*)(g_xl + (size_t)i * 4) = lo;
    } else if (i < X4 + W4) {
        int wi = i - X4;
        int row = wi >> 5, c4 = wi & 31;
        const float* src;
        if      (row < 128) src = Wl1 + (size_t)row * 128;
        else if (row < 256) src = Wr1 + (size_t)(row - 128) * 128;
        else if (row < 384) src = Wl2 + (size_t)(row - 256) * 128;
        else if (row < 512) src = Wr2 + (size_t)(row - 384) * 128;
        else if (row < 544) src = Wl3 + (size_t)(row - 512) * 128;
        else                src = Wr3 + (size_t)(row - 544) * 128;
        float4 v = *(const float4*)(src + c4 * 4);
        uint2 hi, lo; split_pack4(v, hi, lo);
        *(uint2*)(g_wh + row * 128 + c4 * 4) = hi;
        *(uint2*)(g_wl + row * 128 + c4 * 4) = lo;
    }
}

// ---------------- CSR scan ----------------
__global__ void k_scan1() {
    __shared__ int wsum[32];
    int t = threadIdx.x, b = blockIdx.x;
    int i = b * 1024 + t;
    int v = (i < N_NODES) ? g_deg[i] : 0;
    int lane = t & 31, w = t >> 5;
    int x = v;
    #pragma unroll
    for (int o = 1; o < 32; o <<= 1) {
        int y = __shfl_up_sync(0xffffffffu, x, o);
        if (lane >= o) x += y;
    }
    if (lane == 31) wsum[w] = x;
    __syncthreads();
    if (w == 0) {
        int s = wsum[lane];
        #pragma unroll
        for (int o = 1; o < 32; o <<= 1) {
            int y = __shfl_up_sync(0xffffffffu, s, o);
            if (lane >= o) s += y;
        }
        wsum[lane] = s;
    }
    __syncthreads();
    int incl = x + (w > 0 ? wsum[w - 1] : 0);
    if (i < N_NODES) {
        g_off[i + 1] = incl;
        g_inv[i] = (v > 0) ? (1.0f / (float)v) : 0.0f;
    }
    if (t == 1023) g_bsum[b] = incl;
}

// finalize offsets; block-local bsum prefix inline (b>>2 const per 256-node block)
__global__ void k_scan3() {
    __shared__ int spre;
    int b = blockIdx.x;
    int t = threadIdx.x;
    int need = b >> 2;
    if (t < 32) {
        int v = (t < need) ? g_bsum[t] : 0;
        if (t + 32 < need) v += g_bsum[t + 32];
        #pragma unroll
        for (int o = 16; o > 0; o >>= 1)
            v += __shfl_xor_sync(0xffffffffu, v, o);
        if (t == 0) spre = v;
    }
    __syncthreads();
    int i = b * 256 + t;
    if (i < N_NODES) {
        int o = g_off[i + 1] + spre;
        g_off[i + 1] = o;
        g_pos[i] = o - g_deg[i];
    }
    if (i == 0) g_off[0] = 0;
}

__global__ void k_scatter(const int* __restrict__ src, const int* __restrict__ dst) {
    int e = blockIdx.x * blockDim.x + threadIdx.x;
    if (e < N_EDGES) {
        int d = dst[e];
        int p = atomicAdd(&g_pos[d], 1);
        g_srcs[p] = src[e];
    }
}

// ------- mean aggregation over bf16 HI plane only (half the gather bytes) -------
// accumulates in fp32; emits mean as bf16 hi/lo planes for the GEMM
__global__ void k_agg_bf(const __nv_bfloat16* __restrict__ ph,
                         __nv_bfloat16* __restrict__ oh,
                         __nv_bfloat16* __restrict__ ol) {
    int w    = (blockIdx.x * blockDim.x + threadIdx.x) >> 5;
    int lane = threadIdx.x & 31;
    if (w >= N_NODES) return;

    int e  = g_off[w];
    int e1 = g_off[w + 1];
    float4 acc = make_float4(0.f, 0.f, 0.f, 0.f);
    const __nv_bfloat16* base = ph + lane * 4;

    for (; e + 3 < e1; e += 4) {
        int s0 = g_srcs[e], s1 = g_srcs[e + 1], s2 = g_srcs[e + 2], s3 = g_srcs[e + 3];
        float4 v0 = bf4_to_f4(*(const uint2*)(base + (size_t)s0 * 128));
        float4 v1 = bf4_to_f4(*(const uint2*)(base + (size_t)s1 * 128));
        float4 v2 = bf4_to_f4(*(const uint2*)(base + (size_t)s2 * 128));
        float4 v3 = bf4_to_f4(*(const uint2*)(base + (size_t)s3 * 128));
        acc.x += (v0.x + v1.x) + (v2.x + v3.x);
        acc.y += (v0.y + v1.y) + (v2.y + v3.y);
        acc.z += (v0.z + v1.z) + (v2.z + v3.z);
        acc.w += (v0.w + v1.w) + (v2.w + v3.w);
    }
    for (; e < e1; e++) {
        float4 v = bf4_to_f4(*(const uint2*)(base + (size_t)g_srcs[e] * 128));
        acc.x += v.x; acc.y += v.y; acc.z += v.z; acc.w += v.w;
    }

    float inv = g_inv[w];
    float4 o = make_float4(acc.x * inv, acc.y * inv, acc.z * inv, acc.w * inv);
    uint2 hi, lo; split_pack4(o, hi, lo);
    *(uint2*)(oh + (size_t)w * 128 + lane * 4) = hi;
    *(uint2*)(ol + (size_t)w * 128 + lane * 4) = lo;
}

// ---------------- plane -> smem copies (synchronous, proven) ----------------
__device__ __forceinline__ void load_A_plane(
    __nv_bfloat16* smb, const __nv_bfloat16* __restrict__ ph,
    const __nv_bfloat16* __restrict__ pl, int row0, int kc, int t)
{
    int m = t >> 1, kh = (t & 1) * 32;
    int r = row0 + m;
    int off = m * A_STRIDE + kh;
    if (r < N_NODES) {
        const uint4* gh = (const uint4*)(ph + (size_t)r * 128 + kc + kh);
        const uint4* gl = (const uint4*)(pl + (size_t)r * 128 + kc + kh);
        #pragma unroll
        for (int i = 0; i < 4; i++) {
            *(uint4*)(smb + SM_AH + off + i * 8) = gh[i];
            *(uint4*)(smb + SM_AL + off + i * 8) = gl[i];
        }
    } else {
        uint4 z = make_uint4(0, 0, 0, 0);
        #pragma unroll
        for (int i = 0; i < 4; i++) {
            *(uint4*)(smb + SM_AH + off + i * 8) = z;
            *(uint4*)(smb + SM_AL + off + i * 8) = z;
        }
    }
}

__device__ __forceinline__ void load_W_plane(
    __nv_bfloat16* smb, int wrow0, int kc, int t)
{
    int j = t >> 2, kh = (t & 3) * 16;
    int off = j * A_STRIDE + kh;
    const uint4* gh = (const uint4*)(g_wh + (size_t)(wrow0 + j) * 128 + kc + kh);
    const uint4* gl = (const uint4*)(g_wl + (size_t)(wrow0 + j) * 128 + kc + kh);
    #pragma unroll
    for (int i = 0; i < 2; i++) {
        *(uint4*)(smb + SM_WH + off + i * 8) = gh[i];
        *(uint4*)(smb + SM_WL + off + i * 8) = gl[i];
    }
}

// one K=64 chunk of bf16x3 mma
__device__ __forceinline__ void mma_chunk(
    const __nv_bfloat16* smb, int wm, int wn, int lane, float c[2][4][4])
{
    #pragma unroll
    for (int kf = 0; kf < 4; kf++) {
        int kcol = kf * 16 + (lane & 3) * 2;
        uint32_t ah[2][4], al[2][4];
        #pragma unroll
        for (int mt = 0; mt < 2; mt++) {
            int base = (wm * 32 + mt * 16 + (lane >> 2)) * A_STRIDE + kcol;
            ah[mt][0] = *(const uint32_t*)(smb + SM_AH + base);
            ah[mt][1] = *(const uint32_t*)(smb + SM_AH + base + 8 * A_STRIDE);
            ah[mt][2] = *(const uint32_t*)(smb + SM_AH + base + 8);
            ah[mt][3] = *(const uint32_t*)(smb + SM_AH + base + 8 * A_STRIDE + 8);
            al[mt][0] = *(const uint32_t*)(smb + SM_AL + base);
            al[mt][1] = *(const uint32_t*)(smb + SM_AL + base + 8 * A_STRIDE);
            al[mt][2] = *(const uint32_t*)(smb + SM_AL + base + 8);
            al[mt][3] = *(const uint32_t*)(smb + SM_AL + base + 8 * A_STRIDE + 8);
        }
        uint32_t bh[4][2], bl[4][2];
        #pragma unroll
        for (int nt = 0; nt < 4; nt++) {
            int base = (wn * 32 + nt * 8 + (lane >> 2)) * A_STRIDE + kcol;
            bh[nt][0] = *(const uint32_t*)(smb + SM_WH + base);
            bh[nt][1] = *(const uint32_t*)(smb + SM_WH + base + 8);
            bl[nt][0] = *(const uint32_t*)(smb + SM_WL + base);
            bl[nt][1] = *(const uint32_t*)(smb + SM_WL + base + 8);
        }
        #pragma unroll
        for (int mt = 0; mt < 2; mt++)
            #pragma unroll
            for (int nt = 0; nt < 4; nt++) {
                MMA_BF16(c[mt][nt], ah[mt], bh[nt]);
                MMA_BF16(c[mt][nt], al[mt], bh[nt]);
                MMA_BF16(c[mt][nt], ah[mt], bl[nt]);
            }
    }
}

// ---------- dual GEMM + bias + relu (layers 1 & 2), synchronous loads -------
__global__ __launch_bounds__(256) void k_gemmJ_mma(
    const __nv_bfloat16* __restrict__ mh, const __nv_bfloat16* __restrict__ ml,
    const __nv_bfloat16* __restrict__ rh, const __nv_bfloat16* __restrict__ rl,
    int wl_row, int wr_row, const float* __restrict__ bias,
    __nv_bfloat16* __restrict__ outh, __nv_bfloat16* __restrict__ outl)
{
    extern __shared__ __nv_bfloat16 smb[];
    const int t    = threadIdx.x;
    const int lane = t & 31;
    const int w    = t >> 5;
    const int wm   = w & 3;
    const int wn   = w >> 2;
    const int row0 = blockIdx.x * 128;
    const int n0   = blockIdx.y * 64;

    float c[2][4][4];
    #pragma unroll
    for (int mt = 0; mt < 2; mt++)
        #pragma unroll
        for (int nt = 0; nt < 4; nt++)
            #pragma unroll
            for (int i = 0; i < 4; i++) c[mt][nt][i] = 0.f;

    #pragma unroll 1
    for (int ph = 0; ph < 2; ph++) {
        const __nv_bfloat16* ahp = ph ? rh : mh;
        const __nv_bfloat16* alp = ph ? rl : ml;
        const int wr0 = (ph ? wr_row : wl_row) + n0;
        #pragma unroll 1
        for (int ck = 0; ck < 2; ck++) {
            const int kc = ck * 64;
            load_A_plane(smb, ahp, alp, row0, kc, t);
            load_W_plane(smb, wr0, kc, t);
            __syncthreads();
            mma_chunk(smb, wm, wn, lane, c);
            __syncthreads();
        }
    }

    #pragma unroll
    for (int mt = 0; mt < 2; mt++) {
        int r0 = row0 + wm * 32 + mt * 16 + (lane >> 2);
        #pragma unroll
        for (int nt = 0; nt < 4; nt++) {
            int col = n0 + wn * 32 + nt * 8 + (lane & 3) * 2;
            float b0 = bias[col], b1 = bias[col + 1];
            if (r0 < N_NODES) {
                float f0 = fmaxf(c[mt][nt][0] + b0, 0.f);
                float f1 = fmaxf(c[mt][nt][1] + b1, 0.f);
                uint32_t hi, lo; split2(f0, f1, hi, lo);
                *(uint32_t*)(outh + (size_t)r0 * 128 + col) = hi;
                *(uint32_t*)(outl + (size_t)r0 * 128 + col) = lo;
            }
            if (r0 + 8 < N_NODES) {
                float f2 = fmaxf(c[mt][nt][2] + b0, 0.f);
                float f3 = fmaxf(c[mt][nt][3] + b1, 0.f);
                uint32_t hi, lo; split2(f2, f3, hi, lo);
                *(uint32_t*)(outh + (size_t)(r0 + 8) * 128 + col) = hi;
                *(uint32_t*)(outl + (size_t)(r0 + 8) * 128 + col) = lo;
            }
        }
    }
}

// ---------- layer-3 pair GEMM: p = h2@Wl3^T, q = h2@Wr3^T + b ----------
__global__ __launch_bounds__(256) void k_gemm3_mma(
    const __nv_bfloat16* __restrict__ ah, const __nv_bfloat16* __restrict__ al,
    const float* __restrict__ bias,
    float* __restrict__ p, float* __restrict__ q)
{
    extern __shared__ __nv_bfloat16 smb[];
    const int t    = threadIdx.x;
    const int lane = t & 31;
    const int w    = t >> 5;
    const int wm   = w & 3;
    const int wn   = w >> 2;      // 0 -> p, 1 -> q
    const int row0 = blockIdx.x * 128;

    float c[2][4][4];
    #pragma unroll
    for (int mt = 0; mt < 2; mt++)
        #pragma unroll
        for (int nt = 0; nt < 4; nt++)
            #pragma unroll
            for (int i = 0; i < 4; i++) c[mt][nt][i] = 0.f;

    #pragma unroll 1
    for (int ck = 0; ck < 2; ck++) {
        const int kc = ck * 64;
        load_A_plane(smb, ah, al, row0, kc, t);
        load_W_plane(smb, 512, kc, t);
        __syncthreads();
        mma_chunk(smb, wm, wn, lane, c);
        __syncthreads();
    }

    float* dstm = (wn == 0) ? p : q;
    #pragma unroll
    for (int mt = 0; mt < 2; mt++) {
        int r0 = row0 + wm * 32 + mt * 16 + (lane >> 2);
        #pragma unroll
        for (int nt = 0; nt < 4; nt++) {
            int col = nt * 8 + (lane & 3) * 2;
            float b0 = (wn == 1) ? bias[col]     : 0.f;
            float b1 = (wn == 1) ? bias[col + 1] : 0.f;
            if (r0 < N_NODES)
                *(float2*)(dstm + (size_t)r0 * 32 + col) =
                    make_float2(c[mt][nt][0] + b0, c[mt][nt][1] + b1);
            if (r0 + 8 < N_NODES)
                *(float2*)(dstm + (size_t)(r0 + 8) * 32 + col) =
                    make_float2(c[mt][nt][2] + b0, c[mt][nt][3] + b1);
        }
    }
}

// ---------------- layer-3 aggregation in 32-d + final relu ----------------
__global__ void k_agg3(const float* __restrict__ p, const float* __restrict__ q,
                       float* __restrict__ out) {
    int w    = (blockIdx.x * blockDim.x + threadIdx.x) >> 5;
    int lane = threadIdx.x & 31;
    if (w >= N_NODES) return;

    int e  = g_off[w];
    int e1 = g_off[w + 1];
    float acc = 0.f;
    for (; e + 3 < e1; e += 4) {
        int s0 = g_srcs[e], s1 = g_srcs[e + 1], s2 = g_srcs[e + 2], s3 = g_srcs[e + 3];
        acc += (p[(size_t)s0 * 32 + lane] + p[(size_t)s1 * 32 + lane])
             + (p[(size_t)s2 * 32 + lane] + p[(size_t)s3 * 32 + lane]);
    }
    for (; e < e1; e++) acc += p[(size_t)g_srcs[e] * 32 + lane];

    out[(size_t)w * 32 + lane] = fmaxf(acc * g_inv[w] + q[(size_t)w * 32 + lane], 0.f);
}

// ---------------- launch ----------------
extern "C" void kernel_launch(void* const* d_in, const int* in_sizes, int n_in,
                              void* d_out, int out_size) {
    const float* x   = (const float*)d_in[0];
    const int*   ei  = (const int*)d_in[1];
    const float* Wl1 = (const float*)d_in[2];
    const float* bl1 = (const float*)d_in[3];
    const float* Wr1 = (const float*)d_in[4];
    const float* Wl2 = (const float*)d_in[5];
    const float* bl2 = (const float*)d_in[6];
    const float* Wr2 = (const float*)d_in[7];
    const float* Wl3 = (const float*)d_in[8];
    const float* bl3 = (const float*)d_in[9];
    const float* Wr3 = (const float*)d_in[10];
    float* out = (float*)d_out;

    const int* src = ei;
    const int* dst = ei + N_EDGES;

    cudaFuncSetAttribute(k_gemmJ_mma, cudaFuncAttributeMaxDynamicSharedMemorySize, SMEM_MMA);
    cudaFuncSetAttribute(k_gemm3_mma, cudaFuncAttributeMaxDynamicSharedMemorySize, SMEM_MMA);

    int* deg_p;
    float *p_p, *q_p;
    __nv_bfloat16 *xh_p, *xl_p, *mh_p, *ml_p, *h1h_p, *h1l_p, *h2h_p, *h2l_p;
    cudaGetSymbolAddress((void**)&deg_p, g_deg);
    cudaGetSymbolAddress((void**)&p_p,   g_p);
    cudaGetSymbolAddress((void**)&q_p,   g_q);
    cudaGetSymbolAddress((void**)&xh_p,  g_xh);
    cudaGetSymbolAddress((void**)&xl_p,  g_xl);
    cudaGetSymbolAddress((void**)&mh_p,  g_mh);
    cudaGetSymbolAddress((void**)&ml_p,  g_ml);
    cudaGetSymbolAddress((void**)&h1h_p, g_h1h);
    cudaGetSymbolAddress((void**)&h1l_p, g_h1l);
    cudaGetSymbolAddress((void**)&h2h_p, g_h2h);
    cudaGetSymbolAddress((void**)&h2l_p, g_h2l);

    const int AB = (N_NODES * 32 + 255) / 256;
    const int FB = (X4 + W4 + 255) / 256;      // covers N_EDGES too
    dim3 GJ((N_NODES + 127) / 128, 2);
    const int G3 = (N_NODES + 127) / 128;

    // CSR build + operand split
    cudaMemsetAsync(deg_p, 0, N_NODES * sizeof(int));
    k_split_count<<<FB, 256>>>(x, Wl1, Wr1, Wl2, Wr2, Wl3, Wr3, dst);
    k_scan1<<<SCAN_B, 1024>>>();
    k_scan3<<<(N_NODES + 255) / 256, 256>>>();
    k_scatter<<<(N_EDGES + 255) / 256, 256>>>(src, dst);

    // layer 1: gather x hi-plane only (half gather bytes)
    k_agg_bf<<<AB, 256>>>(xh_p, mh_p, ml_p);
    k_gemmJ_mma<<<GJ, 256, SMEM_MMA>>>(mh_p, ml_p, xh_p, xl_p, 0, 128, bl1, h1h_p, h1l_p);
    // layer 2: gather h1 hi-plane only
    k_agg_bf<<<AB, 256>>>(h1h_p, mh_p, ml_p);
    k_gemmJ_mma<<<GJ, 256, SMEM_MMA>>>(mh_p, ml_p, h1h_p, h1l_p, 256, 384, bl2, h2h_p, h2l_p);
    // layer 3
    k_gemm3_mma<<<G3, 256, SMEM_MMA>>>(h2h_p, h2l_p, bl3, p_p, q_p);
    k_agg3<<<AB, 256>>>(p_p, q_p, out);
}